// round 12
// baseline (speedup 1.0000x reference)
#include <cuda_runtime.h>
#include <cstdint>

#define B_     32
#define CIN_   256
#define COUT_  256
#define HW_    56
#define WN_    (COUT_ * CIN_ * 9)
#define BN_EPS 1e-5f

typedef unsigned long long ull;

// Scratch (allocation-free __device__ globals)
__device__ int   g_maxbits;                    // static zero; atomicMax idempotent
__device__ float g_U[16 * CIN_ * COUT_];       // [p][ci][co] Winograd weights
__device__ float g_scale[COUT_];
__device__ float g_bias[COUT_];

// ---------------------------------------------------------------------------
__global__ void wmax_kernel(const float* __restrict__ w) {
    float m = 0.0f;
    for (int i = blockIdx.x * blockDim.x + threadIdx.x; i < WN_;
         i += gridDim.x * blockDim.x)
        m = fmaxf(m, fabsf(w[i]));
    #pragma unroll
    for (int o = 16; o > 0; o >>= 1)
        m = fmaxf(m, __shfl_xor_sync(0xFFFFFFFFu, m, o));
    if ((threadIdx.x & 31) == 0)
        atomicMax(&g_maxbits, __float_as_int(m));   // nonneg: int order ok
}

// DoReFa quant + Winograd weight transform U = G g G^T  (per co,ci)
__global__ void uprep_kernel(const float* __restrict__ w) {
    int idx = blockIdx.x * blockDim.x + threadIdx.x;   // 65536
    int co = idx >> 8, ci = idx & 255;
    float T = tanhf(__int_as_float(g_maxbits));
    float q[3][3];
    #pragma unroll
    for (int ky = 0; ky < 3; ++ky)
        #pragma unroll
        for (int kx = 0; kx < 3; ++kx) {
            float t = tanhf(w[(co * 256 + ci) * 9 + ky * 3 + kx]);
            float u = t / (2.0f * T) + 0.5f;
            q[ky][kx] = 2.0f * (rintf(u * 15.0f) / 15.0f) - 1.0f;
        }
    float a[4][3];
    #pragma unroll
    for (int c = 0; c < 3; ++c) {
        a[0][c] = q[0][c];
        a[1][c] = 0.5f * (q[0][c] + q[1][c] + q[2][c]);
        a[2][c] = 0.5f * (q[0][c] - q[1][c] + q[2][c]);
        a[3][c] = q[2][c];
    }
    #pragma unroll
    for (int i = 0; i < 4; ++i) {
        float u0 = a[i][0];
        float u1 = 0.5f * (a[i][0] + a[i][1] + a[i][2]);
        float u2 = 0.5f * (a[i][0] - a[i][1] + a[i][2]);
        float u3 = a[i][2];
        g_U[((i * 4 + 0) * 256 + ci) * 256 + co] = u0;
        g_U[((i * 4 + 1) * 256 + ci) * 256 + co] = u1;
        g_U[((i * 4 + 2) * 256 + ci) * 256 + co] = u2;
        g_U[((i * 4 + 3) * 256 + ci) * 256 + co] = u3;
    }
}

__global__ void bnprep_kernel(const float* __restrict__ gamma,
                              const float* __restrict__ beta,
                              const float* __restrict__ mean,
                              const float* __restrict__ var) {
    int c = threadIdx.x;
    float inv = gamma[c] * rsqrtf(var[c] + BN_EPS);
    g_scale[c] = inv;
    g_bias[c]  = beta[c] - mean[c] * inv;
}

// ---------------------------------------------------------------------------
#define FFMA2(d, a, b) \
    asm("fma.rn.f32x2 %0, %1, %2, %0;" : "+l"(d) : "l"(a), "l"(b))

static __device__ __forceinline__ void cp16(uint32_t dst, const void* src) {
    asm volatile("cp.async.cg.shared.global [%0], [%1], 16;"
                 :: "r"(dst), "l"(src));
}
#define CP_COMMIT() asm volatile("cp.async.commit_group;")
#define CP_WAIT(n)  asm volatile("cp.async.wait_group %0;" :: "n"(n) : "memory")

// SMEM layout (bytes):
//  W double buf: [ci8][p16] rows of 64co f32 (256B) + 16 pad = 272B  -> 34816 x2
//  V:            [ci8][p16] rows of 16t splat f32x2 + pad    = 144B  -> 18432
//  X stage:      [ci8][10r][12c] f32                                 -> 3840
//  BN:           scale64 + bias64                                    -> 512
//  Epilogue reuse: Msm [p16] stride 4112 (65792) + Ysm [64co][68] (17408)
#define WBUF    34816
#define VS_OFF  69632
#define XS_OFF  88064
#define BN_OFF  91904
#define SMEM_TOT 92416
#define MS_OFF  0
#define YS_OFF  65792

extern __shared__ char smem[];

// ---------------------------------------------------------------------------
// Fused Winograd F(2x2,3x3) conv + BN + PACT.
// CTA: 256 thr, 2/SM. Tile: image n, 4x4 output-tile group (8x8 px), 64-co
// quarter. Thread: p=tid>>4 (point), tg=(tid>>2)&3 (4 tiles), cpg=tid&3
// (8 co-pairs) -> 32 f32x2 accumulators.
// ---------------------------------------------------------------------------
__global__ void __launch_bounds__(256, 2)
conv_wino_kernel(const float* __restrict__ x,
                 const float* __restrict__ alpha,
                 float* __restrict__ out) {
    const int tid = threadIdx.x;
    const int p   = tid >> 4;
    const int tg  = (tid >> 2) & 3;
    const int cpg = tid & 3;
    const int Ty  = blockIdx.x / 7, Tx = blockIdx.x % 7;
    const int coQ = blockIdx.y;
    const int n   = blockIdx.z;
    const int oy  = Ty * 8, ox = Tx * 8;

    const uint32_t sb = (uint32_t)__cvta_generic_to_shared(smem);
    float* Xs = (float*)(smem + XS_OFF);
    float* sScale = (float*)(smem + BN_OFF);
    float* sBias  = (float*)(smem + BN_OFF + 256);
    if (tid < 64) {
        sScale[tid] = g_scale[coQ * 64 + tid];
        sBias[tid]  = g_bias[coQ * 64 + tid];
    }

    const float* xn = x + (size_t)n * CIN_ * 3136;
    const float* Usrc = g_U;   // [p][ci][co]

    ull acc[4][8];
    #pragma unroll
    for (int t = 0; t < 4; ++t)
        #pragma unroll
        for (int c = 0; c < 8; ++c) acc[t][c] = 0ull;

    // transform task: task = tid>>1 -> t=task>>3 (16 tiles), ci=task&7
    const int ttile = (tid >> 1) >> 3;
    const int tci   = (tid >> 1) & 7;
    const int thalf = tid & 1;           // V rows {0,1} or {2,3}
    const int tty   = ttile >> 2, ttx = ttile & 3;

    // ---- prologue: stage X chunk 0, issue W chunk 0 ----
    for (int k = 0; k < 4; ++k) {
        int i = tid + k * 256;
        if (i < 800) {
            int ci = i / 100, rem = i - ci * 100, rr = rem / 10, cc = rem - rr * 10;
            int gy = oy - 1 + rr, gx = ox - 1 + cc;
            float v = 0.0f;
            if (gy >= 0 && gy < HW_ && gx >= 0 && gx < HW_)
                v = xn[(size_t)ci * 3136 + gy * 56 + gx];
            Xs[ci * 120 + rr * 12 + cc] = v;
        }
    }
    for (int k = 0; k < 8; ++k) {
        int i = tid + k * 256;           // 2048 granules
        int pp = i >> 7, ci = (i >> 4) & 7, g16 = i & 15;
        cp16(sb + ci * 4352 + pp * 272 + g16 * 16,
             Usrc + ((size_t)(pp * 256 + ci) * 256) + coQ * 64 + g16 * 4);
    }
    CP_COMMIT();
    __syncthreads();

    for (int ch = 0; ch < 32; ++ch) {
        const int buf = ch & 1;
        // ---- V transform (reads Xs, writes Vs) ----
        {
            const float* d = Xs + tci * 120 + (2 * tty) * 12 + 2 * ttx;
            float t0[4], t1[4];          // two temp rows for this half
            #pragma unroll
            for (int c = 0; c < 4; ++c) {
                float d0 = d[0 * 12 + c], d1 = d[1 * 12 + c];
                float d2 = d[2 * 12 + c], d3 = d[3 * 12 + c];
                if (thalf == 0) { t0[c] = d0 - d2; t1[c] = d1 + d2; }
                else            { t0[c] = d2 - d1; t1[c] = d1 - d3; }
            }
            char* vb = smem + VS_OFF + tci * 2304 + ttile * 8;
            const int i0 = thalf * 2;
            float2 v;
            v.x = v.y = t0[0] - t0[2];
            *(float2*)(vb + ((i0 * 4 + 0) * 144)) = v;
            v.x = v.y = t0[1] + t0[2];
            *(float2*)(vb + ((i0 * 4 + 1) * 144)) = v;
            v.x = v.y = t0[2] - t0[1];
            *(float2*)(vb + ((i0 * 4 + 2) * 144)) = v;
            v.x = v.y = t0[1] - t0[3];
            *(float2*)(vb + ((i0 * 4 + 3) * 144)) = v;
            v.x = v.y = t1[0] - t1[2];
            *(float2*)(vb + (((i0 + 1) * 4 + 0) * 144)) = v;
            v.x = v.y = t1[1] + t1[2];
            *(float2*)(vb + (((i0 + 1) * 4 + 1) * 144)) = v;
            v.x = v.y = t1[2] - t1[1];
            *(float2*)(vb + (((i0 + 1) * 4 + 2) * 144)) = v;
            v.x = v.y = t1[1] - t1[3];
            *(float2*)(vb + (((i0 + 1) * 4 + 3) * 144)) = v;
        }

        // ---- prefetch next chunk: W cp.async + X LDG into regs ----
        float xv[4];
        if (ch < 31) {
            const float* Un = Usrc + (size_t)(ch + 1) * 8 * 256;  // ci0 advance
            uint32_t dst = sb + (buf ^ 1) * WBUF;
            for (int k = 0; k < 8; ++k) {
                int i = tid + k * 256;
                int pp = i >> 7, ci = (i >> 4) & 7, g16 = i & 15;
                cp16(dst + ci * 4352 + pp * 272 + g16 * 16,
                     Usrc + ((size_t)(pp * 256 + (ch + 1) * 8 + ci) * 256) +
                         coQ * 64 + g16 * 4);
            }
            CP_COMMIT();
            const float* xc = xn + (size_t)(ch + 1) * 8 * 3136;
            #pragma unroll
            for (int k = 0; k < 4; ++k) {
                int i = tid + k * 256;
                if (i < 800) {
                    int ci = i / 100, rem = i - ci * 100;
                    int rr = rem / 10, cc = rem - rr * 10;
                    int gy = oy - 1 + rr, gx = ox - 1 + cc;
                    xv[k] = 0.0f;
                    if (gy >= 0 && gy < HW_ && gx >= 0 && gx < HW_)
                        xv[k] = xc[(size_t)ci * 3136 + gy * 56 + gx];
                }
            }
            CP_WAIT(1);
        } else {
            CP_WAIT(0);
        }
        __syncthreads();                 // Vs + W[ch] visible

        // ---- GEMM: M[p][t][cp] += V[p][t][ci] * U[p][ci][cp] ----
        {
            const char* vb = smem + VS_OFF + p * 144 + tg * 32;
            const char* wb = smem + buf * WBUF + p * 272 + cpg * 64;
            #pragma unroll
            for (int ci = 0; ci < 8; ++ci) {
                ulonglong2 va = *(const ulonglong2*)(vb + ci * 2304);
                ulonglong2 vc = *(const ulonglong2*)(vb + ci * 2304 + 16);
                ull v2[4] = { va.x, va.y, vc.x, vc.y };
                ulonglong2 w0 = *(const ulonglong2*)(wb + ci * 4352);
                ulonglong2 w1 = *(const ulonglong2*)(wb + ci * 4352 + 16);
                ulonglong2 w2 = *(const ulonglong2*)(wb + ci * 4352 + 32);
                ulonglong2 w3 = *(const ulonglong2*)(wb + ci * 4352 + 48);
                ull w2a[8] = { w0.x, w0.y, w1.x, w1.y, w2.x, w2.y, w3.x, w3.y };
                #pragma unroll
                for (int t = 0; t < 4; ++t)
                    #pragma unroll
                    for (int c = 0; c < 8; ++c)
                        FFMA2(acc[t][c], v2[t], w2a[c]);
            }
        }

        // ---- store prefetched X (Xs free: transform done before sync) ----
        if (ch < 31) {
            #pragma unroll
            for (int k = 0; k < 4; ++k) {
                int i = tid + k * 256;
                if (i < 800) {
                    int ci = i / 100, rem = i - ci * 100;
                    int rr = rem / 10, cc = rem - rr * 10;
                    Xs[ci * 120 + rr * 12 + cc] = xv[k];
                }
            }
        }
        __syncthreads();                 // Xs[ch+1] visible; GEMM done
    }

    // ---- epilogue: M -> smem, inverse transform, BN+PACT, coalesced STG ----
    {
        char* mb = smem + MS_OFF + p * 4112;
        #pragma unroll
        for (int t = 0; t < 4; ++t)
            #pragma unroll
            for (int c = 0; c < 8; ++c)
                *(ull*)(mb + (tg * 4 + t) * 256 + (cpg * 8 + c) * 8) = acc[t][c];
    }
    __syncthreads();

    const float aV   = __ldg(alpha);
    const float r15a = 15.0f / aV;
    const float a15  = aV / 15.0f;
    float* Ys = (float*)(smem + YS_OFF);

    for (int k = 0; k < 2; ++k) {
        int task = tid + k * 256;        // 512 = 16t x 32cp
        int t = task >> 5, cp = task & 31;
        int ty = t >> 2, tx = t & 3;
        float m0[16], m1[16];
        #pragma unroll
        for (int pp = 0; pp < 16; ++pp) {
            ull mv = *(ull*)(smem + MS_OFF + pp * 4112 + t * 256 + cp * 8);
            asm("mov.b64 {%0, %1}, %2;" : "=f"(m0[pp]), "=f"(m1[pp]) : "l"(mv));
        }
        #pragma unroll
        for (int comp = 0; comp < 2; ++comp) {
            const float* m = comp ? m1 : m0;
            const int col = cp * 2 + comp;
            const float sc = sScale[col], bi = sBias[col];
            float r0[4], r1[4];
            #pragma unroll
            for (int j = 0; j < 4; ++j) {
                r0[j] = m[0 * 4 + j] + m[1 * 4 + j] + m[2 * 4 + j];
                r1[j] = m[1 * 4 + j] - m[2 * 4 + j] - m[3 * 4 + j];
            }
            float y00 = r0[0] + r0[1] + r0[2];
            float y01 = r0[1] - r0[2] - r0[3];
            float y10 = r1[0] + r1[1] + r1[2];
            float y11 = r1[1] - r1[2] - r1[3];
            #pragma unroll
            for (int dy = 0; dy < 2; ++dy)
                #pragma unroll
                for (int dx = 0; dx < 2; ++dx) {
                    float v = (dy ? (dx ? y11 : y10) : (dx ? y01 : y00));
                    v = v * sc + bi;
                    v = fminf(fmaxf(v, 0.0f), aV);
                    v = rintf(v * r15a) * a15;
                    Ys[col * 68 + (2 * ty + dy) * 8 + 2 * tx + dx] = v;
                }
        }
    }
    __syncthreads();

    float* ob = out + (size_t)(n * COUT_ + coQ * 64) * 3136 + oy * 56 + ox;
    #pragma unroll
    for (int k = 0; k < 4; ++k) {
        int idx = tid + k * 256;          // 1024 = 64co x 8row x 2
        int co = idx >> 4, q = idx & 15, row = q >> 1, xh = q & 1;
        float4 v4 = *(float4*)(Ys + co * 68 + row * 8 + xh * 4);
        *(float4*)(ob + (size_t)co * 3136 + row * 56 + xh * 4) = v4;
    }
}

// ---------------------------------------------------------------------------
extern "C" void kernel_launch(void* const* d_in, const int* in_sizes, int n_in,
                              void* d_out, int out_size) {
    const float* x      = (const float*)d_in[0];
    const float* weight = (const float*)d_in[1];
    const float* gamma  = (const float*)d_in[2];
    const float* beta   = (const float*)d_in[3];
    const float* rmean  = (const float*)d_in[4];
    const float* rvar   = (const float*)d_in[5];
    const float* alpha  = (const float*)d_in[6];
    float* out = (float*)d_out;

    wmax_kernel<<<576, 256>>>(weight);
    uprep_kernel<<<256, 256>>>(weight);
    bnprep_kernel<<<1, 256>>>(gamma, beta, rmean, rvar);

    cudaFuncSetAttribute(conv_wino_kernel,
                         cudaFuncAttributeMaxDynamicSharedMemorySize, SMEM_TOT);
    dim3 grid(49, 4, B_);
    conv_wino_kernel<<<grid, 256, SMEM_TOT>>>(x, alpha, out);
}

// round 13
// speedup vs baseline: 1.8704x; 1.8704x over previous
#include <cuda_runtime.h>
#include <cstdint>

#define B_     32
#define CIN_   256
#define COUT_  256
#define HW_    56
#define WN_    (COUT_ * CIN_ * 9)
#define BN_EPS 1e-5f

typedef unsigned long long ull;

// Scratch (allocation-free __device__ globals)
__device__ int   g_maxbits;                    // static zero; atomicMax idempotent
__device__ float g_U[16 * CIN_ * COUT_];       // [p][ci][co] Winograd weights
__device__ float g_scale[COUT_];
__device__ float g_bias[COUT_];

// ---------------------------------------------------------------------------
__global__ void wmax_kernel(const float* __restrict__ w) {
    float m = 0.0f;
    for (int i = blockIdx.x * blockDim.x + threadIdx.x; i < WN_;
         i += gridDim.x * blockDim.x)
        m = fmaxf(m, fabsf(w[i]));
    #pragma unroll
    for (int o = 16; o > 0; o >>= 1)
        m = fmaxf(m, __shfl_xor_sync(0xFFFFFFFFu, m, o));
    if ((threadIdx.x & 31) == 0)
        atomicMax(&g_maxbits, __float_as_int(m));   // nonneg: int order ok
}

// DoReFa quant + Winograd weight transform U = G g G^T  (per co,ci)
__global__ void uprep_kernel(const float* __restrict__ w) {
    int idx = blockIdx.x * blockDim.x + threadIdx.x;   // 65536
    int co = idx >> 8, ci = idx & 255;
    float T = tanhf(__int_as_float(g_maxbits));
    float q[3][3];
    #pragma unroll
    for (int ky = 0; ky < 3; ++ky)
        #pragma unroll
        for (int kx = 0; kx < 3; ++kx) {
            float t = tanhf(w[(co * 256 + ci) * 9 + ky * 3 + kx]);
            float u = t / (2.0f * T) + 0.5f;
            q[ky][kx] = 2.0f * (rintf(u * 15.0f) / 15.0f) - 1.0f;
        }
    float a[4][3];
    #pragma unroll
    for (int c = 0; c < 3; ++c) {
        a[0][c] = q[0][c];
        a[1][c] = 0.5f * (q[0][c] + q[1][c] + q[2][c]);
        a[2][c] = 0.5f * (q[0][c] - q[1][c] + q[2][c]);
        a[3][c] = q[2][c];
    }
    #pragma unroll
    for (int i = 0; i < 4; ++i) {
        float u0 = a[i][0];
        float u1 = 0.5f * (a[i][0] + a[i][1] + a[i][2]);
        float u2 = 0.5f * (a[i][0] - a[i][1] + a[i][2]);
        float u3 = a[i][2];
        g_U[((i * 4 + 0) * 256 + ci) * 256 + co] = u0;
        g_U[((i * 4 + 1) * 256 + ci) * 256 + co] = u1;
        g_U[((i * 4 + 2) * 256 + ci) * 256 + co] = u2;
        g_U[((i * 4 + 3) * 256 + ci) * 256 + co] = u3;
    }
}

__global__ void bnprep_kernel(const float* __restrict__ gamma,
                              const float* __restrict__ beta,
                              const float* __restrict__ mean,
                              const float* __restrict__ var) {
    int c = threadIdx.x;
    float inv = gamma[c] * rsqrtf(var[c] + BN_EPS);
    g_scale[c] = inv;
    g_bias[c]  = beta[c] - mean[c] * inv;
}

// ---------------------------------------------------------------------------
#define FFMA2(d, a, b) \
    asm("fma.rn.f32x2 %0, %1, %2, %0;" : "+l"(d) : "l"(a), "l"(b))

static __device__ __forceinline__ void cp16(uint32_t dst, const void* src) {
    asm volatile("cp.async.cg.shared.global [%0], [%1], 16;"
                 :: "r"(dst), "l"(src));
}
#define CP_COMMIT() asm volatile("cp.async.commit_group;")
#define CP_WAIT(n)  asm volatile("cp.async.wait_group %0;" :: "n"(n) : "memory")

// SMEM layout (bytes):
//  W double buf: [ci8][64 slots x 80B]  (slot = p*4+cpg; 20w stride -> CF)
//                5120/ci -> 40960 per buf, x2 = 81920
//  V:            [ci8 x 2320][16p x 144B]  (580w ci-stride ≡ 4 mod 32)
//  X stage:      [ci8][10r][12c] f32 = 3840
//  BN:           512
//  Epilogue reuse: Msm [16p x 4112] = 65792, Ysm [64co][68] = 17408
#define WD_SZ   40960
#define VS_OFF  (2 * WD_SZ)            // 81920
#define VS_CI   2320
#define XS_OFF  (VS_OFF + 8 * VS_CI)   // 100480
#define BN_OFF  (XS_OFF + 3840)        // 104320
#define SMEM_TOT (BN_OFF + 512)        // 104832  (2 CTAs/SM)
#define MS_OFF  0
#define YS_OFF  65792

extern __shared__ char smem[];

// ---------------------------------------------------------------------------
// Fused Winograd F(2x2,3x3) conv + BN + PACT.  CTA: 256 thr, 2/SM.
// Tile: image n, 4x4 output-tile group (8x8 px), 64-co quarter.
// GEMM thread: p=tid>>4, tg=(tid>>2)&3 (4 tiles), cpg=tid&3 (8 co-pairs)
//   -> 32 f32x2 accumulators. All GEMM smem reads bank-conflict-free.
// ---------------------------------------------------------------------------
__global__ void __launch_bounds__(256, 2)
conv_wino_kernel(const float* __restrict__ x,
                 const float* __restrict__ alpha,
                 float* __restrict__ out) {
    const int tid = threadIdx.x;
    const int p   = tid >> 4;
    const int tg  = (tid >> 2) & 3;
    const int cpg = tid & 3;
    const int Ty  = blockIdx.x / 7, Tx = blockIdx.x % 7;
    const int coQ = blockIdx.y;
    const int n   = blockIdx.z;
    const int oy  = Ty * 8, ox = Tx * 8;

    const uint32_t sb = (uint32_t)__cvta_generic_to_shared(smem);
    float* Xs = (float*)(smem + XS_OFF);
    float* sScale = (float*)(smem + BN_OFF);
    float* sBias  = (float*)(smem + BN_OFF + 256);
    if (tid < 64) {
        sScale[tid] = g_scale[coQ * 64 + tid];
        sBias[tid]  = g_bias[coQ * 64 + tid];
    }

    const float* xn = x + (size_t)n * CIN_ * 3136;
    const float* Usrc = g_U;   // [p][ci][co]

    ull acc[4][8];
    #pragma unroll
    for (int t = 0; t < 4; ++t)
        #pragma unroll
        for (int c = 0; c < 8; ++c) acc[t][c] = 0ull;

    // transform task split
    const int ttile = (tid >> 1) >> 3;
    const int tci   = (tid >> 1) & 7;
    const int thalf = tid & 1;           // V rows {0..7} or {8..15}
    const int tty   = ttile >> 2, ttx = ttile & 3;

    // ---- prologue: stage X chunk 0, issue W chunk 0 ----
    for (int k = 0; k < 4; ++k) {
        int i = tid + k * 256;
        if (i < 800) {
            int ci = i / 100, rem = i - ci * 100, rr = rem / 10, cc = rem - rr * 10;
            int gy = oy - 1 + rr, gx = ox - 1 + cc;
            float v = 0.0f;
            if (gy >= 0 && gy < HW_ && gx >= 0 && gx < HW_)
                v = xn[(size_t)ci * 3136 + gy * 56 + gx];
            Xs[ci * 120 + rr * 12 + cc] = v;
        }
    }
    // W: 2048 granules: ci=i>>8, p=(i>>4)&15, cpg=(i>>2)&3, g=i&3
    for (int k = 0; k < 8; ++k) {
        int i = tid + k * 256;
        int ci = i >> 8, pp = (i >> 4) & 15, cq = (i >> 2) & 3, g = i & 3;
        cp16(sb + ci * 5120 + (pp * 4 + cq) * 80 + g * 16,
             Usrc + ((size_t)(pp * 256 + ci) * 256) + coQ * 64 + cq * 16 + g * 4);
    }
    CP_COMMIT();
    __syncthreads();

    for (int ch = 0; ch < 32; ++ch) {
        const int buf = ch & 1;
        // ---- V transform (reads Xs, writes Vs) ----
        {
            const float* d = Xs + tci * 120 + (2 * tty) * 12 + 2 * ttx;
            float t0[4], t1[4];
            #pragma unroll
            for (int c = 0; c < 4; ++c) {
                float d0 = d[0 * 12 + c], d1 = d[1 * 12 + c];
                float d2 = d[2 * 12 + c], d3 = d[3 * 12 + c];
                if (thalf == 0) { t0[c] = d0 - d2; t1[c] = d1 + d2; }
                else            { t0[c] = d2 - d1; t1[c] = d1 - d3; }
            }
            char* vb = smem + VS_OFF + tci * VS_CI + ttile * 8;
            const int i0 = thalf * 2;
            float2 v;
            v.x = v.y = t0[0] - t0[2];
            *(float2*)(vb + ((i0 * 4 + 0) * 144)) = v;
            v.x = v.y = t0[1] + t0[2];
            *(float2*)(vb + ((i0 * 4 + 1) * 144)) = v;
            v.x = v.y = t0[2] - t0[1];
            *(float2*)(vb + ((i0 * 4 + 2) * 144)) = v;
            v.x = v.y = t0[1] - t0[3];
            *(float2*)(vb + ((i0 * 4 + 3) * 144)) = v;
            v.x = v.y = t1[0] - t1[2];
            *(float2*)(vb + (((i0 + 1) * 4 + 0) * 144)) = v;
            v.x = v.y = t1[1] + t1[2];
            *(float2*)(vb + (((i0 + 1) * 4 + 1) * 144)) = v;
            v.x = v.y = t1[2] - t1[1];
            *(float2*)(vb + (((i0 + 1) * 4 + 2) * 144)) = v;
            v.x = v.y = t1[1] - t1[3];
            *(float2*)(vb + (((i0 + 1) * 4 + 3) * 144)) = v;
        }

        // ---- prefetch next chunk: W cp.async + X LDG into regs ----
        float xv[4];
        if (ch < 31) {
            uint32_t dst = sb + (buf ^ 1) * WD_SZ;
            for (int k = 0; k < 8; ++k) {
                int i = tid + k * 256;
                int ci = i >> 8, pp = (i >> 4) & 15, cq = (i >> 2) & 3, g = i & 3;
                cp16(dst + ci * 5120 + (pp * 4 + cq) * 80 + g * 16,
                     Usrc + ((size_t)(pp * 256 + (ch + 1) * 8 + ci) * 256) +
                         coQ * 64 + cq * 16 + g * 4);
            }
            CP_COMMIT();
            const float* xc = xn + (size_t)(ch + 1) * 8 * 3136;
            #pragma unroll
            for (int k = 0; k < 4; ++k) {
                int i = tid + k * 256;
                if (i < 800) {
                    int ci = i / 100, rem = i - ci * 100;
                    int rr = rem / 10, cc = rem - rr * 10;
                    int gy = oy - 1 + rr, gx = ox - 1 + cc;
                    xv[k] = 0.0f;
                    if (gy >= 0 && gy < HW_ && gx >= 0 && gx < HW_)
                        xv[k] = xc[(size_t)ci * 3136 + gy * 56 + gx];
                }
            }
            CP_WAIT(1);
        } else {
            CP_WAIT(0);
        }
        __syncthreads();                 // Vs + W[ch] visible

        // ---- GEMM: M[p][t][cp] += V[p][t][ci] * U[p][ci][cp] ----
        {
            const char* vb = smem + VS_OFF + p * 144 + tg * 32;
            const char* wb = smem + buf * WD_SZ + (p * 4 + cpg) * 80;
            #pragma unroll
            for (int ci = 0; ci < 8; ++ci) {
                ulonglong2 va = *(const ulonglong2*)(vb + ci * VS_CI);
                ulonglong2 vc = *(const ulonglong2*)(vb + ci * VS_CI + 16);
                ull v2[4] = { va.x, va.y, vc.x, vc.y };
                ulonglong2 w0 = *(const ulonglong2*)(wb + ci * 5120);
                ulonglong2 w1 = *(const ulonglong2*)(wb + ci * 5120 + 16);
                ulonglong2 w2 = *(const ulonglong2*)(wb + ci * 5120 + 32);
                ulonglong2 w3 = *(const ulonglong2*)(wb + ci * 5120 + 48);
                ull w2a[8] = { w0.x, w0.y, w1.x, w1.y, w2.x, w2.y, w3.x, w3.y };
                #pragma unroll
                for (int t = 0; t < 4; ++t)
                    #pragma unroll
                    for (int c = 0; c < 8; ++c)
                        FFMA2(acc[t][c], v2[t], w2a[c]);
            }
        }

        // ---- store prefetched X ----
        if (ch < 31) {
            #pragma unroll
            for (int k = 0; k < 4; ++k) {
                int i = tid + k * 256;
                if (i < 800) {
                    int ci = i / 100, rem = i - ci * 100;
                    int rr = rem / 10, cc = rem - rr * 10;
                    Xs[ci * 120 + rr * 12 + cc] = xv[k];
                }
            }
        }
        __syncthreads();                 // Xs[ch+1] visible; GEMM done
    }

    // ---- epilogue: M -> smem, inverse transform, BN+PACT, coalesced STG ----
    {
        char* mb = smem + MS_OFF + p * 4112;
        #pragma unroll
        for (int t = 0; t < 4; ++t)
            #pragma unroll
            for (int c = 0; c < 8; ++c)
                *(ull*)(mb + (tg * 4 + t) * 256 + (cpg * 8 + c) * 8) = acc[t][c];
    }
    __syncthreads();

    const float aV   = __ldg(alpha);
    const float r15a = 15.0f / aV;
    const float a15  = aV / 15.0f;
    float* Ys = (float*)(smem + YS_OFF);

    for (int k = 0; k < 2; ++k) {
        int task = tid + k * 256;        // 512 = 16t x 32cp
        int t = task >> 5, cp = task & 31;
        int ty = t >> 2, tx = t & 3;
        float m0[16], m1[16];
        #pragma unroll
        for (int pp = 0; pp < 16; ++pp) {
            ull mv = *(ull*)(smem + MS_OFF + pp * 4112 + t * 256 + cp * 8);
            asm("mov.b64 {%0, %1}, %2;" : "=f"(m0[pp]), "=f"(m1[pp]) : "l"(mv));
        }
        #pragma unroll
        for (int comp = 0; comp < 2; ++comp) {
            const float* m = comp ? m1 : m0;
            const int col = cp * 2 + comp;
            const float sc = sScale[col], bi = sBias[col];
            float r0[4], r1[4];
            #pragma unroll
            for (int j = 0; j < 4; ++j) {
                r0[j] = m[0 * 4 + j] + m[1 * 4 + j] + m[2 * 4 + j];
                r1[j] = m[1 * 4 + j] - m[2 * 4 + j] - m[3 * 4 + j];
            }
            float y00 = r0[0] + r0[1] + r0[2];
            float y01 = r0[1] - r0[2] - r0[3];
            float y10 = r1[0] + r1[1] + r1[2];
            float y11 = r1[1] - r1[2] - r1[3];
            #pragma unroll
            for (int dy = 0; dy < 2; ++dy)
                #pragma unroll
                for (int dx = 0; dx < 2; ++dx) {
                    float v = (dy ? (dx ? y11 : y10) : (dx ? y01 : y00));
                    v = v * sc + bi;
                    v = fminf(fmaxf(v, 0.0f), aV);
                    v = rintf(v * r15a) * a15;
                    Ys[col * 68 + (2 * ty + dy) * 8 + 2 * tx + dx] = v;
                }
        }
    }
    __syncthreads();

    float* ob = out + (size_t)(n * COUT_ + coQ * 64) * 3136 + oy * 56 + ox;
    #pragma unroll
    for (int k = 0; k < 4; ++k) {
        int idx = tid + k * 256;          // 1024 = 64co x 8row x 2
        int co = idx >> 4, q = idx & 15, row = q >> 1, xh = q & 1;
        float4 v4 = *(float4*)(Ys + co * 68 + row * 8 + xh * 4);
        *(float4*)(ob + (size_t)co * 3136 + row * 56 + xh * 4) = v4;
    }
}

// ---------------------------------------------------------------------------
extern "C" void kernel_launch(void* const* d_in, const int* in_sizes, int n_in,
                              void* d_out, int out_size) {
    const float* x      = (const float*)d_in[0];
    const float* weight = (const float*)d_in[1];
    const float* gamma  = (const float*)d_in[2];
    const float* beta   = (const float*)d_in[3];
    const float* rmean  = (const float*)d_in[4];
    const float* rvar   = (const float*)d_in[5];
    const float* alpha  = (const float*)d_in[6];
    float* out = (float*)d_out;

    wmax_kernel<<<576, 256>>>(weight);
    uprep_kernel<<<256, 256>>>(weight);
    bnprep_kernel<<<1, 256>>>(gamma, beta, rmean, rvar);

    cudaFuncSetAttribute(conv_wino_kernel,
                         cudaFuncAttributeMaxDynamicSharedMemorySize, SMEM_TOT);
    dim3 grid(49, 4, B_);
    conv_wino_kernel<<<grid, 256, SMEM_TOT>>>(x, alpha, out);
}

// round 14
// speedup vs baseline: 1.9088x; 1.0205x over previous
#include <cuda_runtime.h>
#include <cstdint>

#define B_     32
#define CIN_   256
#define COUT_  256
#define HW_    56
#define WN_    (COUT_ * CIN_ * 9)
#define BN_EPS 1e-5f

typedef unsigned long long ull;

// Scratch (allocation-free __device__ globals)
__device__ int   g_maxbits;                    // static zero; atomicMax idempotent
__device__ float g_U[16 * CIN_ * COUT_];       // [p][ci][co] Winograd weights
__device__ float g_scale[COUT_];
__device__ float g_bias[COUT_];

// ---------------------------------------------------------------------------
__global__ void wmax_kernel(const float* __restrict__ w) {
    float m = 0.0f;
    for (int i = blockIdx.x * blockDim.x + threadIdx.x; i < WN_;
         i += gridDim.x * blockDim.x)
        m = fmaxf(m, fabsf(w[i]));
    #pragma unroll
    for (int o = 16; o > 0; o >>= 1)
        m = fmaxf(m, __shfl_xor_sync(0xFFFFFFFFu, m, o));
    if ((threadIdx.x & 31) == 0)
        atomicMax(&g_maxbits, __float_as_int(m));   // nonneg: int order ok
}

// DoReFa quant + Winograd weight transform U = G g G^T  (per co,ci)
__global__ void uprep_kernel(const float* __restrict__ w) {
    int idx = blockIdx.x * blockDim.x + threadIdx.x;   // 65536
    int co = idx >> 8, ci = idx & 255;
    float T = tanhf(__int_as_float(g_maxbits));
    float q[3][3];
    #pragma unroll
    for (int ky = 0; ky < 3; ++ky)
        #pragma unroll
        for (int kx = 0; kx < 3; ++kx) {
            float t = tanhf(w[(co * 256 + ci) * 9 + ky * 3 + kx]);
            float u = t / (2.0f * T) + 0.5f;
            q[ky][kx] = 2.0f * (rintf(u * 15.0f) / 15.0f) - 1.0f;
        }
    float a[4][3];
    #pragma unroll
    for (int c = 0; c < 3; ++c) {
        a[0][c] = q[0][c];
        a[1][c] = 0.5f * (q[0][c] + q[1][c] + q[2][c]);
        a[2][c] = 0.5f * (q[0][c] - q[1][c] + q[2][c]);
        a[3][c] = q[2][c];
    }
    #pragma unroll
    for (int i = 0; i < 4; ++i) {
        float u0 = a[i][0];
        float u1 = 0.5f * (a[i][0] + a[i][1] + a[i][2]);
        float u2 = 0.5f * (a[i][0] - a[i][1] + a[i][2]);
        float u3 = a[i][2];
        g_U[((i * 4 + 0) * 256 + ci) * 256 + co] = u0;
        g_U[((i * 4 + 1) * 256 + ci) * 256 + co] = u1;
        g_U[((i * 4 + 2) * 256 + ci) * 256 + co] = u2;
        g_U[((i * 4 + 3) * 256 + ci) * 256 + co] = u3;
    }
}

__global__ void bnprep_kernel(const float* __restrict__ gamma,
                              const float* __restrict__ beta,
                              const float* __restrict__ mean,
                              const float* __restrict__ var) {
    int c = threadIdx.x;
    float inv = gamma[c] * rsqrtf(var[c] + BN_EPS);
    g_scale[c] = inv;
    g_bias[c]  = beta[c] - mean[c] * inv;
}

// ---------------------------------------------------------------------------
#define FFMA2(d, a, b) \
    asm("fma.rn.f32x2 %0, %1, %2, %0;" : "+l"(d) : "l"(a), "l"(b))

static __device__ __forceinline__ void cp16(uint32_t dst, const void* src) {
    asm volatile("cp.async.cg.shared.global [%0], [%1], 16;"
                 :: "r"(dst), "l"(src));
}
#define CP_COMMIT() asm volatile("cp.async.commit_group;")
#define CP_WAIT(n)  asm volatile("cp.async.wait_group %0;" :: "n"(n) : "memory")

// SMEM layout (bytes):
//  W double buf: [ci8][p16][co64] f32, 4096/ci -> 32768 per buf, x2 = 65536
//  V: [ci8 pad 5136][p16 x 320][lt4 x 80][k7 x 8]  (f32x2 splats)  = 41088
//  X stage: [ci8 pad 164f][10r][16c] f32                           = 5248
//  Epilogue overlay: M [p16 x 7616][tile28 x 272][cp32 x 8]        = 121856
//  BN beyond M: 512
#define WD_SZ   32768
#define VS_OFF  65536
#define VS_CI   5136
#define XS_OFF  106624
#define XS_CI   164                    /* floats */
#define BN_OFF  121856
#define SMEM_TOT 122368
#define MP_STR  7616
#define MT_STR  272

extern __shared__ char smem[];

// ---------------------------------------------------------------------------
// Fused Winograd F(2x2,3x3) conv + BN + PACT.  CTA: 512 thr, 1/SM.
// Tile: image n, 14x8 px region (7x4=28 tiles), 64-co quarter.
// GEMM: warp = one p (16 warps = 16 p); lane = lt(4 tile-lanes) x lc(8 co-
// lanes); thread = 7 tiles x 4 co-pairs = 28 f32x2 accs. V reads broadcast
// across lc, W reads broadcast across lt -> crossbar ~27% of FFMA2 cycles.
// ---------------------------------------------------------------------------
__global__ void __launch_bounds__(512, 1)
conv_wino_kernel(const float* __restrict__ x,
                 const float* __restrict__ alpha,
                 float* __restrict__ out) {
    const int tid  = threadIdx.x;
    const int p    = tid >> 5;
    const int lane = tid & 31;
    const int lt   = lane >> 3;
    const int lc   = lane & 7;
    const int rx   = blockIdx.x & 3, ry = blockIdx.x >> 2;
    const int coQ  = blockIdx.y;
    const int n    = blockIdx.z;
    const int ox   = rx * 14, oy = ry * 8;

    const uint32_t sb = (uint32_t)__cvta_generic_to_shared(smem);
    float* Xs = (float*)(smem + XS_OFF);
    float* sScale = (float*)(smem + BN_OFF);
    float* sBias  = (float*)(smem + BN_OFF + 256);
    if (tid < 64) {
        sScale[tid] = g_scale[coQ * 64 + tid];
        sBias[tid]  = g_bias[coQ * 64 + tid];
    }

    const float* xn = x + (size_t)n * CIN_ * 3136;

    ull acc[7][4];
    #pragma unroll
    for (int t = 0; t < 7; ++t)
        #pragma unroll
        for (int c = 0; c < 4; ++c) acc[t][c] = 0ull;

    // transform task split: 448 = 28 tiles x 8 ci x 2 half
    const int ttile = tid >> 4;          // 0..31 (use <28*16=448)
    const int tci   = (tid >> 1) & 7;
    const int thalf = tid & 1;
    const int tty   = ttile / 7, ttx = ttile % 7;

    // ---- prologue: stage X chunk 0 (direct), W chunk 0 (cp.async) ----
    #pragma unroll
    for (int k = 0; k < 3; ++k) {
        int i = tid + k * 512;
        if (i < 1280) {
            int ci = i / 160, rem = i % 160, r = rem >> 4, c = rem & 15;
            int gy = oy - 1 + r, gx = ox - 1 + c;
            float v = 0.0f;
            if (gy >= 0 && gy < HW_ && gx >= 0 && gx < HW_)
                v = xn[(size_t)ci * 3136 + gy * 56 + gx];
            Xs[ci * XS_CI + r * 16 + c] = v;
        }
    }
    // W: 2048 granules of 16B: ci=i>>8, p=(i>>4)&15, g=i&15
    #pragma unroll
    for (int k = 0; k < 4; ++k) {
        int i = tid + k * 512;
        int ci = i >> 8, pp = (i >> 4) & 15, g = i & 15;
        cp16(sb + ci * 4096 + pp * 256 + g * 16,
             g_U + ((size_t)(pp * 256 + ci) * 256) + coQ * 64 + g * 4);
    }
    CP_COMMIT();
    __syncthreads();

    for (int ch = 0; ch < 32; ++ch) {
        const int buf = ch & 1;
        // ---- V transform (reads Xs, writes Vs) ----
        if (tid < 448) {
            const float* d = Xs + tci * XS_CI + (2 * tty) * 16 + 2 * ttx;
            float t0[4], t1[4];
            #pragma unroll
            for (int c = 0; c < 4; ++c) {
                float d0 = d[0 * 16 + c], d1 = d[1 * 16 + c];
                float d2 = d[2 * 16 + c], d3 = d[3 * 16 + c];
                if (thalf == 0) { t0[c] = d0 - d2; t1[c] = d1 + d2; }
                else            { t0[c] = d2 - d1; t1[c] = d1 - d3; }
            }
            char* vb = smem + VS_OFF + tci * VS_CI +
                       (ttile / 7) * 80 + (ttile % 7) * 8;
            const int i0 = thalf * 2;
            float2 v;
            v.x = v.y = t0[0] - t0[2]; *(float2*)(vb + (i0*4+0)*320) = v;
            v.x = v.y = t0[1] + t0[2]; *(float2*)(vb + (i0*4+1)*320) = v;
            v.x = v.y = t0[2] - t0[1]; *(float2*)(vb + (i0*4+2)*320) = v;
            v.x = v.y = t0[1] - t0[3]; *(float2*)(vb + (i0*4+3)*320) = v;
            v.x = v.y = t1[0] - t1[2]; *(float2*)(vb + ((i0+1)*4+0)*320) = v;
            v.x = v.y = t1[1] + t1[2]; *(float2*)(vb + ((i0+1)*4+1)*320) = v;
            v.x = v.y = t1[2] - t1[1]; *(float2*)(vb + ((i0+1)*4+2)*320) = v;
            v.x = v.y = t1[1] - t1[3]; *(float2*)(vb + ((i0+1)*4+3)*320) = v;
        }

        // ---- prefetch next chunk: W cp.async + X LDG into regs ----
        float xv[3];
        if (ch < 31) {
            uint32_t dst = sb + (buf ^ 1) * WD_SZ;
            #pragma unroll
            for (int k = 0; k < 4; ++k) {
                int i = tid + k * 512;
                int ci = i >> 8, pp = (i >> 4) & 15, g = i & 15;
                cp16(dst + ci * 4096 + pp * 256 + g * 16,
                     g_U + ((size_t)(pp * 256 + (ch + 1) * 8 + ci) * 256) +
                         coQ * 64 + g * 4);
            }
            CP_COMMIT();
            const float* xc = xn + (size_t)(ch + 1) * 8 * 3136;
            #pragma unroll
            for (int k = 0; k < 3; ++k) {
                int i = tid + k * 512;
                if (i < 1280) {
                    int ci = i / 160, rem = i % 160, r = rem >> 4, c = rem & 15;
                    int gy = oy - 1 + r, gx = ox - 1 + c;
                    xv[k] = 0.0f;
                    if (gy >= 0 && gy < HW_ && gx >= 0 && gx < HW_)
                        xv[k] = xc[(size_t)ci * 3136 + gy * 56 + gx];
                }
            }
            CP_WAIT(1);
        } else {
            CP_WAIT(0);
        }
        __syncthreads();                 // Vs + W[ch] visible

        // ---- GEMM: acc[t][cp] += V[p][lt*7+t] * W[p][co pair] ----
        {
            const char* vbase = smem + VS_OFF + p * 320 + lt * 80;
            const char* wbase = smem + buf * WD_SZ + p * 256 + lc * 32;
            #pragma unroll
            for (int ci = 0; ci < 8; ++ci) {
                const char* vc = vbase + ci * VS_CI;
                ulonglong2 a0 = *(const ulonglong2*)(vc);
                ulonglong2 a1 = *(const ulonglong2*)(vc + 16);
                ulonglong2 a2 = *(const ulonglong2*)(vc + 32);
                ull a3 = *(const ull*)(vc + 48);
                ull v[7] = { a0.x, a0.y, a1.x, a1.y, a2.x, a2.y, a3 };
                const char* wc = wbase + ci * 4096;
                ulonglong2 w0 = *(const ulonglong2*)(wc);
                ulonglong2 w1 = *(const ulonglong2*)(wc + 16);
                ull w[4] = { w0.x, w0.y, w1.x, w1.y };
                #pragma unroll
                for (int t = 0; t < 7; ++t)
                    #pragma unroll
                    for (int c = 0; c < 4; ++c)
                        FFMA2(acc[t][c], v[t], w[c]);
            }
        }

        // ---- store prefetched X ----
        if (ch < 31) {
            #pragma unroll
            for (int k = 0; k < 3; ++k) {
                int i = tid + k * 512;
                if (i < 1280) {
                    int ci = i / 160, rem = i % 160, r = rem >> 4, c = rem & 15;
                    Xs[ci * XS_CI + r * 16 + c] = xv[k];
                }
            }
        }
        __syncthreads();                 // Xs[ch+1] visible; GEMM done
    }

    // ---- epilogue: M scatter -> inverse transform + BN + PACT -> gmem ----
    {
        char* mb = smem + p * MP_STR;
        #pragma unroll
        for (int k = 0; k < 7; ++k)
            #pragma unroll
            for (int j = 0; j < 4; ++j)
                *(ull*)(mb + (lt * 7 + k) * MT_STR + (lc * 4 + j) * 8) =
                    acc[k][j];
    }
    __syncthreads();

    const float aV   = __ldg(alpha);
    const float r15a = 15.0f / aV;
    const float a15  = aV / 15.0f;

    #pragma unroll
    for (int kk = 0; kk < 2; ++kk) {
        int task = tid + kk * 512;       // 896 = 28 tiles x 32 copairs
        if (task < 896) {
            int cp = task & 31, tile = task >> 5;
            int tty = tile / 7, ttx = tile % 7;
            float m0[16], m1[16];
            #pragma unroll
            for (int pp = 0; pp < 16; ++pp) {
                ull mv = *(ull*)(smem + pp * MP_STR + tile * MT_STR + cp * 8);
                asm("mov.b64 {%0, %1}, %2;" : "=f"(m0[pp]), "=f"(m1[pp])
                    : "l"(mv));
            }
            #pragma unroll
            for (int comp = 0; comp < 2; ++comp) {
                const float* m = comp ? m1 : m0;
                const int col = cp * 2 + comp;
                const float sc = sScale[col], bi = sBias[col];
                float r0[4], r1[4];
                #pragma unroll
                for (int j = 0; j < 4; ++j) {
                    r0[j] = m[0 * 4 + j] + m[1 * 4 + j] + m[2 * 4 + j];
                    r1[j] = m[1 * 4 + j] - m[2 * 4 + j] - m[3 * 4 + j];
                }
                float y00 = r0[0] + r0[1] + r0[2];
                float y01 = r0[1] - r0[2] - r0[3];
                float y10 = r1[0] + r1[1] + r1[2];
                float y11 = r1[1] - r1[2] - r1[3];
                y00 = rintf(fminf(fmaxf(y00 * sc + bi, 0.0f), aV) * r15a) * a15;
                y01 = rintf(fminf(fmaxf(y01 * sc + bi, 0.0f), aV) * r15a) * a15;
                y10 = rintf(fminf(fmaxf(y10 * sc + bi, 0.0f), aV) * r15a) * a15;
                y11 = rintf(fminf(fmaxf(y11 * sc + bi, 0.0f), aV) * r15a) * a15;
                float* op = out + (size_t)(n * COUT_ + coQ * 64 + col) * 3136 +
                            (oy + 2 * tty) * 56 + ox + 2 * ttx;
                *(float2*)(op)      = make_float2(y00, y01);
                *(float2*)(op + 56) = make_float2(y10, y11);
            }
        }
    }
}

// ---------------------------------------------------------------------------
extern "C" void kernel_launch(void* const* d_in, const int* in_sizes, int n_in,
                              void* d_out, int out_size) {
    const float* x      = (const float*)d_in[0];
    const float* weight = (const float*)d_in[1];
    const float* gamma  = (const float*)d_in[2];
    const float* beta   = (const float*)d_in[3];
    const float* rmean  = (const float*)d_in[4];
    const float* rvar   = (const float*)d_in[5];
    const float* alpha  = (const float*)d_in[6];
    float* out = (float*)d_out;

    wmax_kernel<<<576, 256>>>(weight);
    uprep_kernel<<<256, 256>>>(weight);
    bnprep_kernel<<<1, 256>>>(gamma, beta, rmean, rvar);

    cudaFuncSetAttribute(conv_wino_kernel,
                         cudaFuncAttributeMaxDynamicSharedMemorySize, SMEM_TOT);
    dim3 grid(28, 4, B_);
    conv_wino_kernel<<<grid, 512, SMEM_TOT>>>(x, alpha, out);
}